// round 2
// baseline (speedup 1.0000x reference)
#include <cuda_runtime.h>
#include <cstdint>

#define SDIM 1024
#define DDIM 1024
#define BATCH 32

// ---------------- scratch (device globals — no allocation allowed) ----------
__device__ float g_e[(size_t)BATCH * SDIM * SDIM];   // 128 MB similarity matrix
__device__ float g_rmax[BATCH * SDIM];
__device__ float g_rinv[BATCH * SDIM];
__device__ float g_cmax[BATCH * SDIM];
__device__ float g_cinv[BATCH * SDIM];

// ---------------- fast exp on the FMA pipe (avoids MUFU rt=8 bottleneck) ----
// exp(x) = 2^(x*log2e); 2^f via degree-7 poly of e^{f ln2}, f in [0,1).
// Max rel error ~1.3e-6. Valid for x <= 0 (softmax shifted inputs).
__device__ __forceinline__ float fast_exp(float x) {
    float t = x * 1.4426950408889634f;
    t = fmaxf(t, -126.0f);               // clamp: underflow -> ~1e-38 (harmless)
    float n = floorf(t);
    float f = t - n;                     // [0, 1)
    float p = 1.52527338e-5f;
    p = fmaf(p, f, 1.54035304e-4f);
    p = fmaf(p, f, 1.33335581e-3f);
    p = fmaf(p, f, 9.61812911e-3f);
    p = fmaf(p, f, 5.55041087e-2f);
    p = fmaf(p, f, 2.40226507e-1f);
    p = fmaf(p, f, 6.93147181e-1f);
    p = fmaf(p, f, 1.0f);
    return p * __int_as_float(((int)n + 127) << 23);
}

// ---------------- GEMM config ------------------------------------------------
constexpr int BM = 128, BN = 128, BK = 16;
constexpr int TM = 8, TN = 8;            // 16x16 threads = 256

// MODE 0: e = P @ H^T                  A=P (K-contig), B=H (K-contig),  C=g_e
// MODE 1: att_p = softmax_row(e) @ H   A=e (K-contig, row-weighted), B=H (N-contig)
// MODE 2: att_h = softmax_col(e)^T @ P A=e^T (N-contig, col-weighted), B=P (N-contig)
template<int MODE>
__global__ __launch_bounds__(256, 2)
void gemm_kernel(const float* __restrict__ gP,
                 const float* __restrict__ gH,
                 float* __restrict__ gC)
{
    const int b   = blockIdx.z;
    const int m0  = blockIdx.y * BM;
    const int n0  = blockIdx.x * BN;
    const int tid = threadIdx.x;

    const float* A;
    const float* Bp;
    float* C;
    int lda, ldb, ldc, K;

    if constexpr (MODE == 0) {
        A  = gP  + (size_t)b * SDIM * DDIM; lda = DDIM;
        Bp = gH  + (size_t)b * SDIM * DDIM; ldb = DDIM;
        C  = g_e + (size_t)b * SDIM * SDIM; ldc = SDIM; K = DDIM;
    } else if constexpr (MODE == 1) {
        A  = g_e + (size_t)b * SDIM * SDIM; lda = SDIM;
        Bp = gH  + (size_t)b * SDIM * DDIM; ldb = DDIM;
        C  = gC  + (size_t)b * SDIM * DDIM; ldc = DDIM; K = SDIM;
    } else {
        A  = g_e + (size_t)b * SDIM * SDIM; lda = SDIM;   // accessed transposed
        Bp = gP  + (size_t)b * SDIM * DDIM; ldb = DDIM;
        C  = gC  + (size_t)b * SDIM * DDIM; ldc = DDIM; K = SDIM;
    }

    __shared__ float As[BK][BM + 4];
    __shared__ float Bs[BK][BN + 4];
    __shared__ float wMax[BM];
    __shared__ float wInv[BM];

    if constexpr (MODE >= 1) {
        if (tid < BM) {
            const float* mx = (MODE == 1) ? g_rmax : g_cmax;
            const float* iv = (MODE == 1) ? g_rinv : g_cinv;
            wMax[tid] = mx[b * SDIM + m0 + tid];
            wInv[tid] = iv[b * SDIM + m0 + tid];
        }
        __syncthreads();
    }

    float4 ra[2], rb[2];

    auto loadA = [&](int kt) {
#pragma unroll
        for (int u = 0; u < 2; u++) {
            int f = tid + u * 256;
            if constexpr (MODE <= 1) {
                int row = f >> 2;            // m within tile
                int kk  = (f & 3) << 2;
                float4 v = *reinterpret_cast<const float4*>(
                    A + (size_t)(m0 + row) * lda + kt + kk);
                if constexpr (MODE == 1) {
                    float wm = wMax[row], wi = wInv[row];
                    v.x = fast_exp(v.x - wm) * wi;
                    v.y = fast_exp(v.y - wm) * wi;
                    v.z = fast_exp(v.z - wm) * wi;
                    v.w = fast_exp(v.w - wm) * wi;
                }
                ra[u] = v;
            } else {
                int row = f >> 5;            // k within tile
                int col = (f & 31) << 2;     // m (=j) within tile
                float4 v = *reinterpret_cast<const float4*>(
                    A + (size_t)(kt + row) * lda + m0 + col);
                v.x = fast_exp(v.x - wMax[col + 0]) * wInv[col + 0];
                v.y = fast_exp(v.y - wMax[col + 1]) * wInv[col + 1];
                v.z = fast_exp(v.z - wMax[col + 2]) * wInv[col + 2];
                v.w = fast_exp(v.w - wMax[col + 3]) * wInv[col + 3];
                ra[u] = v;
            }
        }
    };

    auto storeA = [&]() {
#pragma unroll
        for (int u = 0; u < 2; u++) {
            int f = tid + u * 256;
            if constexpr (MODE <= 1) {
                int row = f >> 2;
                int kk  = (f & 3) << 2;
                As[kk + 0][row] = ra[u].x;
                As[kk + 1][row] = ra[u].y;
                As[kk + 2][row] = ra[u].z;
                As[kk + 3][row] = ra[u].w;
            } else {
                int row = f >> 5;
                int col = (f & 31) << 2;
                *reinterpret_cast<float4*>(&As[row][col]) = ra[u];
            }
        }
    };

    auto loadB = [&](int kt) {
#pragma unroll
        for (int u = 0; u < 2; u++) {
            int f = tid + u * 256;
            if constexpr (MODE == 0) {
                int row = f >> 2;            // n within tile
                int kk  = (f & 3) << 2;
                rb[u] = *reinterpret_cast<const float4*>(
                    Bp + (size_t)(n0 + row) * ldb + kt + kk);
            } else {
                int row = f >> 5;            // k within tile
                int col = (f & 31) << 2;     // n within tile
                rb[u] = *reinterpret_cast<const float4*>(
                    Bp + (size_t)(kt + row) * ldb + n0 + col);
            }
        }
    };

    auto storeB = [&]() {
#pragma unroll
        for (int u = 0; u < 2; u++) {
            int f = tid + u * 256;
            if constexpr (MODE == 0) {
                int row = f >> 2;
                int kk  = (f & 3) << 2;
                Bs[kk + 0][row] = rb[u].x;
                Bs[kk + 1][row] = rb[u].y;
                Bs[kk + 2][row] = rb[u].z;
                Bs[kk + 3][row] = rb[u].w;
            } else {
                int row = f >> 5;
                int col = (f & 31) << 2;
                *reinterpret_cast<float4*>(&Bs[row][col]) = rb[u];
            }
        }
    };

    float acc[TM][TN] = {};
    const int trow = (tid >> 4) * TM;
    const int tcol = (tid & 15) * TN;

    loadA(0); loadB(0);
    storeA(); storeB();
    __syncthreads();

    for (int kt = 0; kt < K; kt += BK) {
        bool more = (kt + BK) < K;
        if (more) { loadA(kt + BK); loadB(kt + BK); }

#pragma unroll
        for (int k = 0; k < BK; k++) {
            float a[TM], bb[TN];
#pragma unroll
            for (int i = 0; i < TM; i++) a[i] = As[k][trow + i];
#pragma unroll
            for (int j = 0; j < TN; j++) bb[j] = Bs[k][tcol + j];
#pragma unroll
            for (int i = 0; i < TM; i++)
#pragma unroll
                for (int j = 0; j < TN; j++)
                    acc[i][j] = fmaf(a[i], bb[j], acc[i][j]);
        }
        __syncthreads();
        if (more) { storeA(); storeB(); __syncthreads(); }
    }

#pragma unroll
    for (int i = 0; i < TM; i++) {
        float* crow = C + (size_t)(m0 + trow + i) * ldc + n0 + tcol;
        *reinterpret_cast<float4*>(crow) =
            make_float4(acc[i][0], acc[i][1], acc[i][2], acc[i][3]);
        *reinterpret_cast<float4*>(crow + 4) =
            make_float4(acc[i][4], acc[i][5], acc[i][6], acc[i][7]);
    }
}

// ---------------- softmax statistics ----------------------------------------
// One block per (b,i) row: max_j and sum_j exp(e - max).
__global__ void row_stats_kernel() {
    const int row = blockIdx.x;                       // b*SDIM + i
    const float* e = g_e + (size_t)row * SDIM;
    const int tid = threadIdx.x;                      // 256
    float4 v = *reinterpret_cast<const float4*>(e + tid * 4);
    float m = fmaxf(fmaxf(v.x, v.y), fmaxf(v.z, v.w));

    __shared__ float red[256];
    red[tid] = m;
    __syncthreads();
    for (int s = 128; s > 0; s >>= 1) {
        if (tid < s) red[tid] = fmaxf(red[tid], red[tid + s]);
        __syncthreads();
    }
    float rmax = red[0];
    __syncthreads();

    float s = fast_exp(v.x - rmax) + fast_exp(v.y - rmax)
            + fast_exp(v.z - rmax) + fast_exp(v.w - rmax);
    red[tid] = s;
    __syncthreads();
    for (int st = 128; st > 0; st >>= 1) {
        if (tid < st) red[tid] += red[tid + st];
        __syncthreads();
    }
    if (tid == 0) {
        g_rmax[row] = rmax;
        g_rinv[row] = 1.0f / red[0];
    }
}

// Column stats over e: block = (b, 128-column slab). 256 threads sweep 1024
// rows of a 128-wide slab with coalesced float4 loads; per-thread partials for
// 16 (row-group) x 32 (col-group) are reduced through shared memory.
// Two passes (max, then sum) — slab is L2-resident on the second pass.
__global__ __launch_bounds__(256, 4)
void col_stats_kernel() {
    const int b    = blockIdx.y;
    const int c0   = blockIdx.x * 128;               // slab base column
    const int tid  = threadIdx.x;
    const int cg   = tid & 31;                        // column group: 4 cols
    const int rg   = tid >> 5;                        // row group: 8 of them
    const float* e = g_e + (size_t)b * SDIM * SDIM + c0;

    __shared__ float red[8][132];                     // [rowgroup][col]

    // ---- pass 1: max ----
    float4 m4 = make_float4(-3.4e38f, -3.4e38f, -3.4e38f, -3.4e38f);
    for (int i = rg; i < SDIM; i += 8) {
        float4 v = *reinterpret_cast<const float4*>(e + (size_t)i * SDIM + cg * 4);
        m4.x = fmaxf(m4.x, v.x); m4.y = fmaxf(m4.y, v.y);
        m4.z = fmaxf(m4.z, v.z); m4.w = fmaxf(m4.w, v.w);
    }
    *reinterpret_cast<float4*>(&red[rg][cg * 4]) = m4;
    __syncthreads();
    float cmax[4];
    if (rg == 0) {
#pragma unroll
        for (int q = 0; q < 4; q++) {
            float m = red[0][cg * 4 + q];
#pragma unroll
            for (int r = 1; r < 8; r++) m = fmaxf(m, red[r][cg * 4 + q]);
            red[0][cg * 4 + q] = m;
        }
    }
    __syncthreads();
#pragma unroll
    for (int q = 0; q < 4; q++) cmax[q] = red[0][cg * 4 + q];
    __syncthreads();

    // ---- pass 2: sum of exp ----
    float4 s4 = make_float4(0.f, 0.f, 0.f, 0.f);
    for (int i = rg; i < SDIM; i += 8) {
        float4 v = *reinterpret_cast<const float4*>(e + (size_t)i * SDIM + cg * 4);
        s4.x += fast_exp(v.x - cmax[0]);
        s4.y += fast_exp(v.y - cmax[1]);
        s4.z += fast_exp(v.z - cmax[2]);
        s4.w += fast_exp(v.w - cmax[3]);
    }
    *reinterpret_cast<float4*>(&red[rg][cg * 4]) = s4;
    __syncthreads();
    if (rg == 0) {
#pragma unroll
        for (int q = 0; q < 4; q++) {
            float s = red[0][cg * 4 + q];
#pragma unroll
            for (int r = 1; r < 8; r++) s += red[r][cg * 4 + q];
            int j = c0 + cg * 4 + q;
            g_cmax[b * SDIM + j] = cmax[q];
            g_cinv[b * SDIM + j] = 1.0f / s;
        }
    }
}

// ---------------- entry ------------------------------------------------------
extern "C" void kernel_launch(void* const* d_in, const int* in_sizes, int n_in,
                              void* d_out, int out_size) {
    const float* P = (const float*)d_in[0];   // premises    [B,S,D]
    const float* H = (const float*)d_in[1];   // hypothesises[B,S,D]
    float* out_p = (float*)d_out;                              // attention_p
    float* out_h = out_p + (size_t)BATCH * SDIM * DDIM;        // attention_h

    dim3 blk(256);
    dim3 g1(SDIM / BN, SDIM / BM, BATCH);     // e: [S x S] tiles per batch
    gemm_kernel<0><<<g1, blk>>>(P, H, nullptr);

    row_stats_kernel<<<BATCH * SDIM, 256>>>();
    col_stats_kernel<<<dim3(SDIM / 128, BATCH), 256>>>();

    dim3 g2(DDIM / BN, SDIM / BM, BATCH);     // outputs: [S x D] tiles per batch
    gemm_kernel<1><<<g2, blk>>>(P, H, out_p);
    gemm_kernel<2><<<g2, blk>>>(P, H, out_h);
}

// round 4
// speedup vs baseline: 1.9760x; 1.9760x over previous
#include <cuda_runtime.h>
#include <cuda_bf16.h>
#include <cstdint>

#define SDIM 1024
#define BATCH 32

// ---------------- scratch (device globals — no allocation allowed) ----------
__device__ float g_e[(size_t)BATCH * SDIM * SDIM];   // 128 MB similarity matrix
__device__ float g_rmax[BATCH * SDIM];
__device__ float g_rinv[BATCH * SDIM];
__device__ float g_cmax[BATCH * SDIM];
__device__ float g_cinv[BATCH * SDIM];

// ---------------- fast exp on the FMA pipe ----------------------------------
__device__ __forceinline__ float fast_exp(float x) {
    float t = x * 1.4426950408889634f;
    t = fmaxf(t, -126.0f);
    float n = floorf(t);
    float f = t - n;
    float p = 1.52527338e-5f;
    p = fmaf(p, f, 1.54035304e-4f);
    p = fmaf(p, f, 1.33335581e-3f);
    p = fmaf(p, f, 9.61812911e-3f);
    p = fmaf(p, f, 5.55041087e-2f);
    p = fmaf(p, f, 2.40226507e-1f);
    p = fmaf(p, f, 6.93147181e-1f);
    p = fmaf(p, f, 1.0f);
    return p * __int_as_float(((int)n + 127) << 23);
}

// ---------------- warp-level tensor ops (baseline sm_100-legal) --------------
__device__ __forceinline__ void ldm4(uint32_t* r, uint32_t a) {
    asm volatile("ldmatrix.sync.aligned.m8n8.x4.shared.b16 {%0,%1,%2,%3}, [%4];"
                 : "=r"(r[0]), "=r"(r[1]), "=r"(r[2]), "=r"(r[3]) : "r"(a));
}
__device__ __forceinline__ void mma16816(float* d, const uint32_t* a,
                                         const uint32_t* b) {
    asm volatile(
        "mma.sync.aligned.m16n8k16.row.col.f32.bf16.bf16.f32 "
        "{%0,%1,%2,%3}, {%4,%5,%6,%7}, {%8,%9}, {%0,%1,%2,%3};"
        : "+f"(d[0]), "+f"(d[1]), "+f"(d[2]), "+f"(d[3])
        : "r"(a[0]), "r"(a[1]), "r"(a[2]), "r"(a[3]), "r"(b[0]), "r"(b[1]));
}
__device__ __forceinline__ uint32_t smem_u32(const void* p) {
    uint32_t a;
    asm("{ .reg .u64 t; cvta.to.shared.u64 t, %1; cvt.u32.u64 %0, t; }"
        : "=r"(a) : "l"(p));
    return a;
}

// ---------------- split-bf16 pack --------------------------------------------
// x = hi + lo (both bf16). Packs (x0 -> low half, x1 -> high half).
__device__ __forceinline__ void splitpack(float x0, float x1,
                                          uint32_t& hi, uint32_t& lo) {
    __nv_bfloat162 h2 = __floats2bfloat162_rn(x0, x1);
    uint32_t hu = *reinterpret_cast<uint32_t*>(&h2);
    float h0 = __uint_as_float(hu << 16);
    float h1 = __uint_as_float(hu & 0xffff0000u);
    __nv_bfloat162 l2 = __floats2bfloat162_rn(x0 - h0, x1 - h1);
    hi = hu;
    lo = *reinterpret_cast<uint32_t*>(&l2);
}

// ---------------- GEMM config ------------------------------------------------
constexpr int BM = 128, BN = 128, KC = 64;       // KC = bf16 k per chunk
constexpr int NCHUNK = SDIM / KC;                // 16
constexpr int RSTRIDE = 144;                     // 64 bf16 = 128 B + 16 pad (conflict-free)
constexpr int PLANE = 128 * RSTRIDE;             // 18432 B
constexpr int SMEM_DYN = 4 * PLANE;              // 73728 B

// Direct K-major loader: 128 rows x 64 k, k contiguous in gmem.
template<bool W>
__device__ __forceinline__ void load_direct(const float* __restrict__ src,
                                            char* dH, char* dL, int tid,
                                            const float* wM, const float* wI) {
    const int row = tid >> 1, kb = (tid & 1) * 32;
    const float* s = src + (size_t)row * SDIM + kb;
    float wm = 0.f, wi = 0.f;
    if (W) { wm = wM[row]; wi = wI[row]; }
#pragma unroll
    for (int i = 0; i < 8; i++) {
        float4 v = *reinterpret_cast<const float4*>(s + i * 4);
        if (W) {
            v.x = fast_exp(v.x - wm) * wi;
            v.y = fast_exp(v.y - wm) * wi;
            v.z = fast_exp(v.z - wm) * wi;
            v.w = fast_exp(v.w - wm) * wi;
        }
        uint32_t h0, l0, h1, l1;
        splitpack(v.x, v.y, h0, l0);
        splitpack(v.z, v.w, h1, l1);
        const uint32_t off = (uint32_t)row * RSTRIDE + (kb + i * 4) * 2;
        *reinterpret_cast<uint2*>(dH + off) = make_uint2(h0, h1);
        *reinterpret_cast<uint2*>(dL + off) = make_uint2(l0, l1);
    }
}

// Transposed loader: gmem [k][col] (row stride SDIM) -> smem [col][k].
// Warp w owns k-rows [8w, 8w+8); lanes sweep 128 columns.
template<bool W>
__device__ __forceinline__ void load_trans(const float* __restrict__ src,
                                           char* dH, char* dL, int tid,
                                           const float* wM, const float* wI) {
    const int lane = tid & 31, w = tid >> 5;
    const float* s = src + (size_t)w * 8 * SDIM;
#pragma unroll
    for (int cb = 0; cb < 4; cb++) {
        const int c = cb * 32 + lane;
        float x[8];
#pragma unroll
        for (int kk = 0; kk < 8; kk++) x[kk] = s[(size_t)kk * SDIM + c];
        if (W) {
            const float wm = wM[c], wi = wI[c];
#pragma unroll
            for (int kk = 0; kk < 8; kk++) x[kk] = fast_exp(x[kk] - wm) * wi;
        }
        uint32_t h[4], l[4];
#pragma unroll
        for (int q = 0; q < 4; q++) splitpack(x[2 * q], x[2 * q + 1], h[q], l[q]);
        const uint32_t off = (uint32_t)c * RSTRIDE + w * 16;
        *reinterpret_cast<uint4*>(dH + off) = make_uint4(h[0], h[1], h[2], h[3]);
        *reinterpret_cast<uint4*>(dL + off) = make_uint4(l[0], l[1], l[2], l[3]);
    }
}

// MODE 0: e = P @ H^T
// MODE 1: att_p = softmax_row(e) @ H
// MODE 2: att_h = softmax_col(e)^T @ P
template<int MODE>
__global__ __launch_bounds__(256, 2)
void mma_gemm(const float* __restrict__ gP, const float* __restrict__ gH,
              float* __restrict__ gC)
{
    extern __shared__ char smem[];
    char* aH = smem;
    char* aL = smem + PLANE;
    char* bH = smem + 2 * PLANE;
    char* bL = smem + 3 * PLANE;

    __shared__ float wMax[128], wInv[128];

    const int b    = blockIdx.z;
    const int m0   = blockIdx.y * BM;
    const int n0   = blockIdx.x * BN;
    const int tid  = threadIdx.x;
    const int lane = tid & 31, wid = tid >> 5;
    const int wm_  = (wid >> 2) * 64;            // warp row offset (2 rows of warps)
    const int wn_  = (wid & 3) * 32;             // warp col offset (4 cols)

    const float* eB = g_e + (size_t)b * SDIM * SDIM;
    const float* Pb = gP + (size_t)b * SDIM * SDIM;
    const float* Hb = gH + (size_t)b * SDIM * SDIM;

    if (MODE >= 1 && tid < 128) {
        const float* mx = (MODE == 1) ? g_rmax : g_cmax;
        const float* iv = (MODE == 1) ? g_rinv : g_cinv;
        wMax[tid] = mx[b * SDIM + m0 + tid];
        wInv[tid] = iv[b * SDIM + m0 + tid];
    }
    __syncthreads();

    float acc[4][4][4] = {};                      // [mi][na][4]

    const uint32_t aHb = smem_u32(aH), aLb = smem_u32(aL);
    const uint32_t bHb = smem_u32(bH), bLb = smem_u32(bL);
    // per-lane ldmatrix address components
    const uint32_t lrow = (lane & 15);
    const uint32_t lkof = (lane >> 4) * 16;       // byte offset for k-half

    for (int c = 0; c < NCHUNK; c++) {
        const int kt = c * KC;

        if (MODE == 0) {
            load_direct<false>(Pb + (size_t)m0 * SDIM + kt, aH, aL, tid, wMax, wInv);
            load_direct<false>(Hb + (size_t)n0 * SDIM + kt, bH, bL, tid, wMax, wInv);
        } else if (MODE == 1) {
            load_direct<true >(eB + (size_t)m0 * SDIM + kt, aH, aL, tid, wMax, wInv);
            load_trans <false>(Hb + (size_t)kt * SDIM + n0, bH, bL, tid, wMax, wInv);
        } else {
            load_trans <true >(eB + (size_t)kt * SDIM + m0, aH, aL, tid, wMax, wInv);
            load_trans <false>(Pb + (size_t)kt * SDIM + n0, bH, bL, tid, wMax, wInv);
        }
        __syncthreads();

#pragma unroll
        for (int ks = 0; ks < 4; ks++) {
            const uint32_t kby = ks * 32 + lkof;
            // B fragments: 4 n-atoms (n8), hi & lo planes
            uint32_t bh[4][2], bl[4][2];
#pragma unroll
            for (int nj = 0; nj < 2; nj++) {
                const uint32_t boff =
                    (uint32_t)(wn_ + nj * 16 + lrow) * RSTRIDE + kby;
                uint32_t r[4];
                ldm4(r, bHb + boff);
                bh[nj * 2][0] = r[0]; bh[nj * 2][1] = r[2];
                bh[nj * 2 + 1][0] = r[1]; bh[nj * 2 + 1][1] = r[3];
                ldm4(r, bLb + boff);
                bl[nj * 2][0] = r[0]; bl[nj * 2][1] = r[2];
                bl[nj * 2 + 1][0] = r[1]; bl[nj * 2 + 1][1] = r[3];
            }
#pragma unroll
            for (int mi = 0; mi < 4; mi++) {
                const uint32_t aoff =
                    (uint32_t)(wm_ + mi * 16 + lrow) * RSTRIDE + kby;
                uint32_t ah[4], al[4];
                ldm4(ah, aHb + aoff);
                ldm4(al, aLb + aoff);
#pragma unroll
                for (int na = 0; na < 4; na++) {
                    mma16816(acc[mi][na], ah, bh[na]);
                    mma16816(acc[mi][na], al, bh[na]);
                    mma16816(acc[mi][na], ah, bl[na]);
                }
            }
        }
        __syncthreads();
    }

    // ---- epilogue: direct coalesced-ish STG.64 ------------------------------
    float* C = (MODE == 0) ? (g_e + (size_t)b * SDIM * SDIM)
                           : (gC + (size_t)b * SDIM * SDIM);
#pragma unroll
    for (int mi = 0; mi < 4; mi++) {
        const int r = m0 + wm_ + mi * 16 + (lane >> 2);
#pragma unroll
        for (int na = 0; na < 4; na++) {
            const int col = n0 + wn_ + na * 8 + (lane & 3) * 2;
            *reinterpret_cast<float2*>(C + (size_t)r * SDIM + col) =
                make_float2(acc[mi][na][0], acc[mi][na][1]);
            *reinterpret_cast<float2*>(C + (size_t)(r + 8) * SDIM + col) =
                make_float2(acc[mi][na][2], acc[mi][na][3]);
        }
    }
}

// ---------------- softmax statistics -----------------------------------------
__global__ void row_stats_kernel() {
    const int row = blockIdx.x;
    const float* e = g_e + (size_t)row * SDIM;
    const int tid = threadIdx.x;
    float4 v = *reinterpret_cast<const float4*>(e + tid * 4);
    float m = fmaxf(fmaxf(v.x, v.y), fmaxf(v.z, v.w));

    __shared__ float red[256];
    red[tid] = m;
    __syncthreads();
    for (int s = 128; s > 0; s >>= 1) {
        if (tid < s) red[tid] = fmaxf(red[tid], red[tid + s]);
        __syncthreads();
    }
    float rmax = red[0];
    __syncthreads();

    float s = fast_exp(v.x - rmax) + fast_exp(v.y - rmax)
            + fast_exp(v.z - rmax) + fast_exp(v.w - rmax);
    red[tid] = s;
    __syncthreads();
    for (int st = 128; st > 0; st >>= 1) {
        if (tid < st) red[tid] += red[tid + st];
        __syncthreads();
    }
    if (tid == 0) {
        g_rmax[row] = rmax;
        g_rinv[row] = 1.0f / red[0];
    }
}

__global__ __launch_bounds__(256, 4)
void col_stats_kernel() {
    const int b    = blockIdx.y;
    const int c0   = blockIdx.x * 128;
    const int tid  = threadIdx.x;
    const int cg   = tid & 31;
    const int rg   = tid >> 5;
    const float* e = g_e + (size_t)b * SDIM * SDIM + c0;

    __shared__ float red[8][132];

    float4 m4 = make_float4(-3.4e38f, -3.4e38f, -3.4e38f, -3.4e38f);
    for (int i = rg; i < SDIM; i += 8) {
        float4 v = *reinterpret_cast<const float4*>(e + (size_t)i * SDIM + cg * 4);
        m4.x = fmaxf(m4.x, v.x); m4.y = fmaxf(m4.y, v.y);
        m4.z = fmaxf(m4.z, v.z); m4.w = fmaxf(m4.w, v.w);
    }
    *reinterpret_cast<float4*>(&red[rg][cg * 4]) = m4;
    __syncthreads();
    float cmax[4];
    if (rg == 0) {
#pragma unroll
        for (int q = 0; q < 4; q++) {
            float m = red[0][cg * 4 + q];
#pragma unroll
            for (int r = 1; r < 8; r++) m = fmaxf(m, red[r][cg * 4 + q]);
            red[0][cg * 4 + q] = m;
        }
    }
    __syncthreads();
#pragma unroll
    for (int q = 0; q < 4; q++) cmax[q] = red[0][cg * 4 + q];
    __syncthreads();

    float4 s4 = make_float4(0.f, 0.f, 0.f, 0.f);
    for (int i = rg; i < SDIM; i += 8) {
        float4 v = *reinterpret_cast<const float4*>(e + (size_t)i * SDIM + cg * 4);
        s4.x += fast_exp(v.x - cmax[0]);
        s4.y += fast_exp(v.y - cmax[1]);
        s4.z += fast_exp(v.z - cmax[2]);
        s4.w += fast_exp(v.w - cmax[3]);
    }
    *reinterpret_cast<float4*>(&red[rg][cg * 4]) = s4;
    __syncthreads();
    if (rg == 0) {
#pragma unroll
        for (int q = 0; q < 4; q++) {
            float s = red[0][cg * 4 + q];
#pragma unroll
            for (int r = 1; r < 8; r++) s += red[r][cg * 4 + q];
            int j = c0 + cg * 4 + q;
            g_cmax[b * SDIM + j] = cmax[q];
            g_cinv[b * SDIM + j] = 1.0f / s;
        }
    }
}

// ---------------- entry ------------------------------------------------------
extern "C" void kernel_launch(void* const* d_in, const int* in_sizes, int n_in,
                              void* d_out, int out_size) {
    const float* P = (const float*)d_in[0];
    const float* H = (const float*)d_in[1];
    float* out_p = (float*)d_out;
    float* out_h = out_p + (size_t)BATCH * SDIM * SDIM;

    cudaFuncSetAttribute((const void*)mma_gemm<0>,
                         cudaFuncAttributeMaxDynamicSharedMemorySize, SMEM_DYN);
    cudaFuncSetAttribute((const void*)mma_gemm<1>,
                         cudaFuncAttributeMaxDynamicSharedMemorySize, SMEM_DYN);
    cudaFuncSetAttribute((const void*)mma_gemm<2>,
                         cudaFuncAttributeMaxDynamicSharedMemorySize, SMEM_DYN);

    dim3 blk(256);
    dim3 g(SDIM / BN, SDIM / BM, BATCH);          // (8, 8, 32)

    mma_gemm<0><<<g, blk, SMEM_DYN>>>(P, H, nullptr);
    row_stats_kernel<<<BATCH * SDIM, 256>>>();
    col_stats_kernel<<<dim3(SDIM / 128, BATCH), 256>>>();
    mma_gemm<1><<<g, blk, SMEM_DYN>>>(P, H, out_p);
    mma_gemm<2><<<g, blk, SMEM_DYN>>>(P, H, out_h);
}

// round 5
// speedup vs baseline: 2.1543x; 1.0902x over previous
#include <cuda_runtime.h>
#include <cuda_bf16.h>
#include <cstdint>

#define SDIM 1024
#define BATCH 32
typedef __nv_bfloat16 bf16;

constexpr size_t NELEM = (size_t)BATCH * SDIM * SDIM;   // 33.5M

// ---------------- scratch (device globals — no allocation allowed) ----------
__device__ float g_e[NELEM];                       // 128 MB similarity matrix
__device__ float g_rmax[BATCH * SDIM];
__device__ float g_rinv[BATCH * SDIM];
__device__ float g_cmax[BATCH * SDIM];
__device__ float g_cinv[BATCH * SDIM];
// split-bf16 operand planes (hi/lo)
__device__ bf16 g_Ph[NELEM],  g_Pl[NELEM];         // P   [b][i][d]
__device__ bf16 g_Hh[NELEM],  g_Hl[NELEM];         // H   [b][j][d]
__device__ bf16 g_HTh[NELEM], g_HTl[NELEM];        // H^T [b][d][j]
__device__ bf16 g_PTh[NELEM], g_PTl[NELEM];        // P^T [b][d][i]
__device__ bf16 g_Wrh[NELEM], g_Wrl[NELEM];        // row-softmax(e)   [b][i][j]
__device__ bf16 g_Wch[NELEM], g_Wcl[NELEM];        // col-softmax(e)^T [b][j][i]

// ---------------- fast exp on the FMA pipe ----------------------------------
__device__ __forceinline__ float fast_exp(float x) {
    float t = x * 1.4426950408889634f;
    t = fmaxf(t, -126.0f);
    float n = floorf(t);
    float f = t - n;
    float p = 1.52527338e-5f;
    p = fmaf(p, f, 1.54035304e-4f);
    p = fmaf(p, f, 1.33335581e-3f);
    p = fmaf(p, f, 9.61812911e-3f);
    p = fmaf(p, f, 5.55041087e-2f);
    p = fmaf(p, f, 2.40226507e-1f);
    p = fmaf(p, f, 6.93147181e-1f);
    p = fmaf(p, f, 1.0f);
    return p * __int_as_float(((int)n + 127) << 23);
}

// ---------------- low-level helpers ------------------------------------------
__device__ __forceinline__ uint32_t smem_u32(const void* p) {
    uint32_t a;
    asm("{ .reg .u64 t; cvta.to.shared.u64 t, %1; cvt.u32.u64 %0, t; }"
        : "=r"(a) : "l"(p));
    return a;
}
__device__ __forceinline__ void ldm4(uint32_t* r, uint32_t a) {
    asm volatile("ldmatrix.sync.aligned.m8n8.x4.shared.b16 {%0,%1,%2,%3}, [%4];"
                 : "=r"(r[0]), "=r"(r[1]), "=r"(r[2]), "=r"(r[3]) : "r"(a));
}
__device__ __forceinline__ void mma16816(float* d, const uint32_t* a,
                                         const uint32_t* b) {
    asm volatile(
        "mma.sync.aligned.m16n8k16.row.col.f32.bf16.bf16.f32 "
        "{%0,%1,%2,%3}, {%4,%5,%6,%7}, {%8,%9}, {%0,%1,%2,%3};"
        : "+f"(d[0]), "+f"(d[1]), "+f"(d[2]), "+f"(d[3])
        : "r"(a[0]), "r"(a[1]), "r"(a[2]), "r"(a[3]), "r"(b[0]), "r"(b[1]));
}
__device__ __forceinline__ void cp16(uint32_t dst, const void* src) {
    asm volatile("cp.async.cg.shared.global [%0], [%1], 16;"
                 :: "r"(dst), "l"(src));
}
#define CP_COMMIT() asm volatile("cp.async.commit_group;" ::: "memory")
#define CP_WAIT0()  asm volatile("cp.async.wait_group 0;" ::: "memory")
#define CP_WAIT1()  asm volatile("cp.async.wait_group 1;" ::: "memory")

// x = hi + lo (both bf16). Packs (x0 -> low half, x1 -> high half).
__device__ __forceinline__ void splitpack(float x0, float x1,
                                          uint32_t& hi, uint32_t& lo) {
    __nv_bfloat162 h2 = __floats2bfloat162_rn(x0, x1);
    uint32_t hu = *reinterpret_cast<uint32_t*>(&h2);
    float h0 = __uint_as_float(hu << 16);
    float h1 = __uint_as_float(hu & 0xffff0000u);
    __nv_bfloat162 l2 = __floats2bfloat162_rn(x0 - h0, x1 - h1);
    hi = hu;
    lo = *reinterpret_cast<uint32_t*>(&l2);
}

// ---------------- preprocess: fp32 -> split bf16 (direct) --------------------
__global__ __launch_bounds__(256)
void cvt_kernel(const float* __restrict__ X, bf16* __restrict__ Oh,
                bf16* __restrict__ Ol) {
    const size_t i4 = (size_t)blockIdx.x * 256 + threadIdx.x;  // float4 index
    float4 v = reinterpret_cast<const float4*>(X)[i4];
    uint32_t h0, l0, h1, l1;
    splitpack(v.x, v.y, h0, l0);
    splitpack(v.z, v.w, h1, l1);
    reinterpret_cast<uint2*>(Oh)[i4] = make_uint2(h0, h1);
    reinterpret_cast<uint2*>(Ol)[i4] = make_uint2(l0, l1);
}

// ---------------- preprocess: fp32 -> split bf16 transposed ------------------
__global__ __launch_bounds__(256)
void tcvt_kernel(const float* __restrict__ X, bf16* __restrict__ Th,
                 bf16* __restrict__ Tl) {
    const int b = blockIdx.z, r0 = blockIdx.y * 32, c0 = blockIdx.x * 32;
    const int tid = threadIdx.x, tx = tid & 31, ty = tid >> 5;
    __shared__ float t[32][33];
    const float* Xb = X + (size_t)b * SDIM * SDIM;
#pragma unroll
    for (int q = 0; q < 4; q++)
        t[ty + 8 * q][tx] = Xb[(size_t)(r0 + ty + 8 * q) * SDIM + c0 + tx];
    __syncthreads();
#pragma unroll
    for (int q = 0; q < 2; q++) {
        const int u = q * 256 + tid;
        const int oc = u >> 4, ip = u & 15;
        uint32_t hi, lo;
        splitpack(t[2 * ip][oc], t[2 * ip + 1][oc], hi, lo);
        const size_t base = ((size_t)b * SDIM * SDIM + (size_t)(c0 + oc) * SDIM + r0) >> 1;
        reinterpret_cast<uint32_t*>(Th)[base + ip] = hi;
        reinterpret_cast<uint32_t*>(Tl)[base + ip] = lo;
    }
}

// ---------------- preprocess: softmax weights (row direct + col transposed) --
__global__ __launch_bounds__(256)
void weights_kernel() {
    const int b = blockIdx.z, r0 = blockIdx.y * 32, c0 = blockIdx.x * 32;
    const int tid = threadIdx.x, tx = tid & 31, ty = tid >> 5;
    __shared__ float t[32][33];
    __shared__ float rm[32], ri[32], cm[32], ci[32];
    const float* eb = g_e + (size_t)b * SDIM * SDIM;
#pragma unroll
    for (int q = 0; q < 4; q++)
        t[ty + 8 * q][tx] = eb[(size_t)(r0 + ty + 8 * q) * SDIM + c0 + tx];
    if (tid < 32) { rm[tid] = g_rmax[b * SDIM + r0 + tid]; ri[tid] = g_rinv[b * SDIM + r0 + tid]; }
    else if (tid < 64) { cm[tid - 32] = g_cmax[b * SDIM + c0 + tid - 32]; ci[tid - 32] = g_cinv[b * SDIM + c0 + tid - 32]; }
    __syncthreads();
#pragma unroll
    for (int q = 0; q < 2; q++) {
        const int u = q * 256 + tid;
        const int i = u >> 4, jp = u & 15;
        float w0 = fast_exp(t[i][2 * jp] - rm[i]) * ri[i];
        float w1 = fast_exp(t[i][2 * jp + 1] - rm[i]) * ri[i];
        uint32_t hi, lo;
        splitpack(w0, w1, hi, lo);
        const size_t base = ((size_t)b * SDIM * SDIM + (size_t)(r0 + i) * SDIM + c0) >> 1;
        reinterpret_cast<uint32_t*>(g_Wrh)[base + jp] = hi;
        reinterpret_cast<uint32_t*>(g_Wrl)[base + jp] = lo;
    }
#pragma unroll
    for (int q = 0; q < 2; q++) {
        const int u = q * 256 + tid;
        const int oc = u >> 4, ip = u & 15;
        float w0 = fast_exp(t[2 * ip][oc] - cm[oc]) * ci[oc];
        float w1 = fast_exp(t[2 * ip + 1][oc] - cm[oc]) * ci[oc];
        uint32_t hi, lo;
        splitpack(w0, w1, hi, lo);
        const size_t base = ((size_t)b * SDIM * SDIM + (size_t)(c0 + oc) * SDIM + r0) >> 1;
        reinterpret_cast<uint32_t*>(g_Wch)[base + ip] = hi;
        reinterpret_cast<uint32_t*>(g_Wcl)[base + ip] = lo;
    }
}

// ---------------- main tensor GEMM: C = (Ah+Al) @ (Bh+Bl)^T ------------------
// A: [b][m][k] split bf16, B: [b][n][k] split bf16, C: [b][m][n] fp32.
constexpr int BM = 128, BN = 256, KC = 64;
constexpr int NCHUNK = SDIM / KC;                 // 16
constexpr int RSTRIDE = 144;                      // 128 B + 16 pad, conflict-free
constexpr int APL = 128 * RSTRIDE;                // 18432
constexpr int BPL = 256 * RSTRIDE;                // 36864
constexpr int BUFB = 2 * APL + 2 * BPL;           // 110592
constexpr int SMEM_DYN = 2 * BUFB;                // 221184

__device__ __forceinline__ void load_chunk(const bf16* Ah, const bf16* Al,
                                           const bf16* Bh, const bf16* Bl,
                                           uint32_t s, int kt, int tid) {
#pragma unroll
    for (int q = 0; q < 2; q++) {                 // A planes: 128 rows x 8 segs
        const int blk = q * 512 + tid;
        const int row = blk >> 3, seg = blk & 7;
        const size_t go = (size_t)row * SDIM + kt + seg * 8;
        const uint32_t so = row * RSTRIDE + seg * 16;
        cp16(s + so, Ah + go);
        cp16(s + APL + so, Al + go);
    }
#pragma unroll
    for (int q = 0; q < 4; q++) {                 // B planes: 256 rows x 8 segs
        const int blk = q * 512 + tid;
        const int row = blk >> 3, seg = blk & 7;
        const size_t go = (size_t)row * SDIM + kt + seg * 8;
        const uint32_t so = row * RSTRIDE + seg * 16;
        cp16(s + 2 * APL + so, Bh + go);
        cp16(s + 2 * APL + BPL + so, Bl + go);
    }
}

__global__ __launch_bounds__(512, 1)
void gemm_tc(const bf16* __restrict__ Ah_, const bf16* __restrict__ Al_,
             const bf16* __restrict__ Bh_, const bf16* __restrict__ Bl_,
             float* __restrict__ C_)
{
    extern __shared__ char smem[];
    const int b   = blockIdx.z;
    const int m0  = blockIdx.y * BM;
    const int n0  = blockIdx.x * BN;
    const int tid = threadIdx.x;
    const int lane = tid & 31, wid = tid >> 5;    // 16 warps: 4x4
    const int wm_ = (wid >> 2) * 32;
    const int wn_ = (wid & 3) * 64;

    const size_t bb = (size_t)b * SDIM * SDIM;
    const bf16* Ah = Ah_ + bb + (size_t)m0 * SDIM;
    const bf16* Al = Al_ + bb + (size_t)m0 * SDIM;
    const bf16* Bh = Bh_ + bb + (size_t)n0 * SDIM;
    const bf16* Bl = Bl_ + bb + (size_t)n0 * SDIM;

    const uint32_t sb[2] = { smem_u32(smem), smem_u32(smem) + BUFB };

    float acc[2][8][4] = {};

    load_chunk(Ah, Al, Bh, Bl, sb[0], 0, tid);
    CP_COMMIT();

    const uint32_t lrow = lane & 15;
    const uint32_t lkof = (lane >> 4) * 16;

    for (int c = 0; c < NCHUNK; c++) {
        if (c + 1 < NCHUNK) {
            load_chunk(Ah, Al, Bh, Bl, sb[(c + 1) & 1], (c + 1) * KC, tid);
            CP_COMMIT();
            CP_WAIT1();
        } else {
            CP_WAIT0();
        }
        __syncthreads();

        const uint32_t aHb = sb[c & 1];
        const uint32_t aLb = aHb + APL;
        const uint32_t bHb = aHb + 2 * APL;
        const uint32_t bLb = bHb + BPL;

#pragma unroll
        for (int ks = 0; ks < 4; ks++) {
            const uint32_t kby = ks * 32 + lkof;
            uint32_t bh[8][2], bl[8][2];
#pragma unroll
            for (int nj = 0; nj < 4; nj++) {
                const uint32_t boff = (wn_ + nj * 16 + lrow) * RSTRIDE + kby;
                uint32_t r[4];
                ldm4(r, bHb + boff);
                bh[nj * 2][0] = r[0]; bh[nj * 2][1] = r[2];
                bh[nj * 2 + 1][0] = r[1]; bh[nj * 2 + 1][1] = r[3];
                ldm4(r, bLb + boff);
                bl[nj * 2][0] = r[0]; bl[nj * 2][1] = r[2];
                bl[nj * 2 + 1][0] = r[1]; bl[nj * 2 + 1][1] = r[3];
            }
#pragma unroll
            for (int mi = 0; mi < 2; mi++) {
                const uint32_t aoff = (wm_ + mi * 16 + lrow) * RSTRIDE + kby;
                uint32_t ah[4], al[4];
                ldm4(ah, aHb + aoff);
                ldm4(al, aLb + aoff);
#pragma unroll
                for (int na = 0; na < 8; na++) {
                    mma16816(acc[mi][na], ah, bh[na]);
                    mma16816(acc[mi][na], al, bh[na]);
                    mma16816(acc[mi][na], ah, bl[na]);
                }
            }
        }
        __syncthreads();
    }

    // ---- epilogue: direct STG.64 -------------------------------------------
    float* C = C_ + bb;
#pragma unroll
    for (int mi = 0; mi < 2; mi++) {
        const int r = m0 + wm_ + mi * 16 + (lane >> 2);
#pragma unroll
        for (int na = 0; na < 8; na++) {
            const int col = n0 + wn_ + na * 8 + (lane & 3) * 2;
            *reinterpret_cast<float2*>(C + (size_t)r * SDIM + col) =
                make_float2(acc[mi][na][0], acc[mi][na][1]);
            *reinterpret_cast<float2*>(C + (size_t)(r + 8) * SDIM + col) =
                make_float2(acc[mi][na][2], acc[mi][na][3]);
        }
    }
}

// ---------------- softmax statistics -----------------------------------------
__global__ void row_stats_kernel() {
    const int row = blockIdx.x;
    const float* e = g_e + (size_t)row * SDIM;
    const int tid = threadIdx.x;
    float4 v = *reinterpret_cast<const float4*>(e + tid * 4);
    float m = fmaxf(fmaxf(v.x, v.y), fmaxf(v.z, v.w));

    __shared__ float red[256];
    red[tid] = m;
    __syncthreads();
    for (int s = 128; s > 0; s >>= 1) {
        if (tid < s) red[tid] = fmaxf(red[tid], red[tid + s]);
        __syncthreads();
    }
    float rmax = red[0];
    __syncthreads();

    float s = fast_exp(v.x - rmax) + fast_exp(v.y - rmax)
            + fast_exp(v.z - rmax) + fast_exp(v.w - rmax);
    red[tid] = s;
    __syncthreads();
    for (int st = 128; st > 0; st >>= 1) {
        if (tid < st) red[tid] += red[tid + st];
        __syncthreads();
    }
    if (tid == 0) {
        g_rmax[row] = rmax;
        g_rinv[row] = 1.0f / red[0];
    }
}

__global__ __launch_bounds__(256, 4)
void col_stats_kernel() {
    const int b    = blockIdx.y;
    const int c0   = blockIdx.x * 128;
    const int tid  = threadIdx.x;
    const int cg   = tid & 31;
    const int rg   = tid >> 5;
    const float* e = g_e + (size_t)b * SDIM * SDIM + c0;

    __shared__ float red[8][132];

    float4 m4 = make_float4(-3.4e38f, -3.4e38f, -3.4e38f, -3.4e38f);
    for (int i = rg; i < SDIM; i += 8) {
        float4 v = *reinterpret_cast<const float4*>(e + (size_t)i * SDIM + cg * 4);
        m4.x = fmaxf(m4.x, v.x); m4.y = fmaxf(m4.y, v.y);
        m4.z = fmaxf(m4.z, v.z); m4.w = fmaxf(m4.w, v.w);
    }
    *reinterpret_cast<float4*>(&red[rg][cg * 4]) = m4;
    __syncthreads();
    float cmax[4];
    if (rg == 0) {
#pragma unroll
        for (int q = 0; q < 4; q++) {
            float m = red[0][cg * 4 + q];
#pragma unroll
            for (int r = 1; r < 8; r++) m = fmaxf(m, red[r][cg * 4 + q]);
            red[0][cg * 4 + q] = m;
        }
    }
    __syncthreads();
#pragma unroll
    for (int q = 0; q < 4; q++) cmax[q] = red[0][cg * 4 + q];
    __syncthreads();

    float4 s4 = make_float4(0.f, 0.f, 0.f, 0.f);
    for (int i = rg; i < SDIM; i += 8) {
        float4 v = *reinterpret_cast<const float4*>(e + (size_t)i * SDIM + cg * 4);
        s4.x += fast_exp(v.x - cmax[0]);
        s4.y += fast_exp(v.y - cmax[1]);
        s4.z += fast_exp(v.z - cmax[2]);
        s4.w += fast_exp(v.w - cmax[3]);
    }
    *reinterpret_cast<float4*>(&red[rg][cg * 4]) = s4;
    __syncthreads();
    if (rg == 0) {
#pragma unroll
        for (int q = 0; q < 4; q++) {
            float s = red[0][cg * 4 + q];
#pragma unroll
            for (int r = 1; r < 8; r++) s += red[r][cg * 4 + q];
            int j = c0 + cg * 4 + q;
            g_cmax[b * SDIM + j] = cmax[q];
            g_cinv[b * SDIM + j] = 1.0f / s;
        }
    }
}

// ---------------- entry ------------------------------------------------------
extern "C" void kernel_launch(void* const* d_in, const int* in_sizes, int n_in,
                              void* d_out, int out_size) {
    const float* P = (const float*)d_in[0];
    const float* H = (const float*)d_in[1];
    float* out_p = (float*)d_out;
    float* out_h = out_p + NELEM;

    cudaFuncSetAttribute((const void*)gemm_tc,
                         cudaFuncAttributeMaxDynamicSharedMemorySize, SMEM_DYN);

    bf16 *Ph, *Pl, *Hh, *Hl, *HTh, *HTl, *PTh, *PTl, *Wrh, *Wrl, *Wch, *Wcl;
    float* e;
    cudaGetSymbolAddress((void**)&Ph,  g_Ph);  cudaGetSymbolAddress((void**)&Pl,  g_Pl);
    cudaGetSymbolAddress((void**)&Hh,  g_Hh);  cudaGetSymbolAddress((void**)&Hl,  g_Hl);
    cudaGetSymbolAddress((void**)&HTh, g_HTh); cudaGetSymbolAddress((void**)&HTl, g_HTl);
    cudaGetSymbolAddress((void**)&PTh, g_PTh); cudaGetSymbolAddress((void**)&PTl, g_PTl);
    cudaGetSymbolAddress((void**)&Wrh, g_Wrh); cudaGetSymbolAddress((void**)&Wrl, g_Wrl);
    cudaGetSymbolAddress((void**)&Wch, g_Wch); cudaGetSymbolAddress((void**)&Wcl, g_Wcl);
    cudaGetSymbolAddress((void**)&e,   g_e);

    const int cvtBlocks = (int)(NELEM / 4 / 256);             // 32768
    cvt_kernel<<<cvtBlocks, 256>>>(P, Ph, Pl);
    cvt_kernel<<<cvtBlocks, 256>>>(H, Hh, Hl);
    tcvt_kernel<<<dim3(32, 32, BATCH), 256>>>(H, HTh, HTl);
    tcvt_kernel<<<dim3(32, 32, BATCH), 256>>>(P, PTh, PTl);

    dim3 gg(SDIM / BN, SDIM / BM, BATCH);                     // (4, 8, 32)
    gemm_tc<<<gg, 512, SMEM_DYN>>>(Ph, Pl, Hh, Hl, e);        // e = P @ H^T

    row_stats_kernel<<<BATCH * SDIM, 256>>>();
    col_stats_kernel<<<dim3(SDIM / 128, BATCH), 256>>>();
    weights_kernel<<<dim3(32, 32, BATCH), 256>>>();

    gemm_tc<<<gg, 512, SMEM_DYN>>>(Wrh, Wrl, HTh, HTl, out_p);  // softmax_r(e) @ H
    gemm_tc<<<gg, 512, SMEM_DYN>>>(Wch, Wcl, PTh, PTl, out_h);  // softmax_c(e)^T @ P
}

// round 7
// speedup vs baseline: 3.2459x; 1.5067x over previous
#include <cuda_runtime.h>
#include <cuda_fp16.h>
#include <cstdint>

#define SDIM 1024
#define BATCH 32
typedef __half f16;

constexpr size_t NELEM = (size_t)BATCH * SDIM * SDIM;   // 33.5M

// ---------------- scratch (device globals — no allocation allowed) ----------
__device__ float g_e[NELEM];                       // 128 MB similarity matrix
__device__ float g_rmax[BATCH * SDIM];
__device__ float g_rinv[BATCH * SDIM];
__device__ float g_cmax[BATCH * SDIM];
__device__ float g_cinv[BATCH * SDIM];
// split-fp16 planes for GEMM-1 operands
__device__ f16 g_Ph[NELEM], g_Pl[NELEM];           // P   [b][i][d] hi/lo
__device__ f16 g_Hh[NELEM], g_Hl[NELEM];           // H   [b][j][d] hi/lo
// single-fp16 planes for GEMM-2/3 operands
__device__ f16 g_HT[NELEM];                        // H^T [b][d][j]
__device__ f16 g_PT[NELEM];                        // P^T [b][d][i]
__device__ f16 g_Wr[NELEM];                        // row-softmax(e)   [b][i][j]
__device__ f16 g_Wc[NELEM];                        // col-softmax(e)^T [b][j][i]

// ---------------- fast exp on the FMA pipe ----------------------------------
__device__ __forceinline__ float fast_exp(float x) {
    float t = x * 1.4426950408889634f;
    t = fmaxf(t, -126.0f);
    float n = floorf(t);
    float f = t - n;
    float p = 1.52527338e-5f;
    p = fmaf(p, f, 1.54035304e-4f);
    p = fmaf(p, f, 1.33335581e-3f);
    p = fmaf(p, f, 9.61812911e-3f);
    p = fmaf(p, f, 5.55041087e-2f);
    p = fmaf(p, f, 2.40226507e-1f);
    p = fmaf(p, f, 6.93147181e-1f);
    p = fmaf(p, f, 1.0f);
    return p * __int_as_float(((int)n + 127) << 23);
}

// ---------------- low-level helpers ------------------------------------------
__device__ __forceinline__ uint32_t smem_u32(const void* p) {
    uint32_t a;
    asm("{ .reg .u64 t; cvta.to.shared.u64 t, %1; cvt.u32.u64 %0, t; }"
        : "=r"(a) : "l"(p));
    return a;
}
__device__ __forceinline__ void ldm4(uint32_t* r, uint32_t a) {
    asm volatile("ldmatrix.sync.aligned.m8n8.x4.shared.b16 {%0,%1,%2,%3}, [%4];"
                 : "=r"(r[0]), "=r"(r[1]), "=r"(r[2]), "=r"(r[3]) : "r"(a));
}
__device__ __forceinline__ void mma16816(float* d, const uint32_t* a,
                                         const uint32_t* b) {
    asm volatile(
        "mma.sync.aligned.m16n8k16.row.col.f32.f16.f16.f32 "
        "{%0,%1,%2,%3}, {%4,%5,%6,%7}, {%8,%9}, {%0,%1,%2,%3};"
        : "+f"(d[0]), "+f"(d[1]), "+f"(d[2]), "+f"(d[3])
        : "r"(a[0]), "r"(a[1]), "r"(a[2]), "r"(a[3]), "r"(b[0]), "r"(b[1]));
}
__device__ __forceinline__ void cp16(uint32_t dst, const void* src) {
    asm volatile("cp.async.cg.shared.global [%0], [%1], 16;"
                 :: "r"(dst), "l"(src));
}
#define CP_COMMIT() asm volatile("cp.async.commit_group;" ::: "memory")
#define CP_WAIT0()  asm volatile("cp.async.wait_group 0;" ::: "memory")
#define CP_WAIT1()  asm volatile("cp.async.wait_group 1;" ::: "memory")

// fp16 split: x = hi + lo. Packs (x0 -> low half, x1 -> high half).
__device__ __forceinline__ void splitpack(float x0, float x1,
                                          uint32_t& hi, uint32_t& lo) {
    __half2 h2 = __floats2half2_rn(x0, x1);
    float h0 = __half2float(__low2half(h2));
    float h1 = __half2float(__high2half(h2));
    __half2 l2 = __floats2half2_rn(x0 - h0, x1 - h1);
    hi = *reinterpret_cast<uint32_t*>(&h2);
    lo = *reinterpret_cast<uint32_t*>(&l2);
}
__device__ __forceinline__ uint32_t pack_h(float x0, float x1) {
    __half2 h2 = __floats2half2_rn(x0, x1);
    return *reinterpret_cast<uint32_t*>(&h2);
}

// ---------------- preprocess: fp32 -> split fp16 (direct) --------------------
__global__ __launch_bounds__(256)
void cvt_kernel(const float* __restrict__ X, f16* __restrict__ Oh,
                f16* __restrict__ Ol) {
    const size_t i4 = (size_t)blockIdx.x * 256 + threadIdx.x;  // float4 index
    float4 v = reinterpret_cast<const float4*>(X)[i4];
    uint32_t h0, l0, h1, l1;
    splitpack(v.x, v.y, h0, l0);
    splitpack(v.z, v.w, h1, l1);
    reinterpret_cast<uint2*>(Oh)[i4] = make_uint2(h0, h1);
    reinterpret_cast<uint2*>(Ol)[i4] = make_uint2(l0, l1);
}

// ---------------- preprocess: fp32 -> fp16 transposed (single plane) --------
__global__ __launch_bounds__(256)
void tcvt_kernel(const float* __restrict__ X, f16* __restrict__ T) {
    const int b = blockIdx.z, r0 = blockIdx.y * 32, c0 = blockIdx.x * 32;
    const int tid = threadIdx.x, tx = tid & 31, ty = tid >> 5;
    __shared__ float t[32][33];
    const float* Xb = X + (size_t)b * SDIM * SDIM;
#pragma unroll
    for (int q = 0; q < 4; q++)
        t[ty + 8 * q][tx] = Xb[(size_t)(r0 + ty + 8 * q) * SDIM + c0 + tx];
    __syncthreads();
#pragma unroll
    for (int q = 0; q < 2; q++) {
        const int u = q * 256 + tid;
        const int oc = u >> 4, ip = u & 15;
        const size_t base = ((size_t)b * SDIM * SDIM + (size_t)(c0 + oc) * SDIM + r0) >> 1;
        reinterpret_cast<uint32_t*>(T)[base + ip] =
            pack_h(t[2 * ip][oc], t[2 * ip + 1][oc]);
    }
}

// ---------------- preprocess: softmax weights (row direct + col transposed) --
__global__ __launch_bounds__(256)
void weights_kernel() {
    const int b = blockIdx.z, r0 = blockIdx.y * 32, c0 = blockIdx.x * 32;
    const int tid = threadIdx.x, tx = tid & 31, ty = tid >> 5;
    __shared__ float t[32][33];
    __shared__ float rm[32], ri[32], cm[32], ci[32];
    const float* eb = g_e + (size_t)b * SDIM * SDIM;
#pragma unroll
    for (int q = 0; q < 4; q++)
        t[ty + 8 * q][tx] = eb[(size_t)(r0 + ty + 8 * q) * SDIM + c0 + tx];
    if (tid < 32) { rm[tid] = g_rmax[b * SDIM + r0 + tid]; ri[tid] = g_rinv[b * SDIM + r0 + tid]; }
    else if (tid < 64) { cm[tid - 32] = g_cmax[b * SDIM + c0 + tid - 32]; ci[tid - 32] = g_cinv[b * SDIM + c0 + tid - 32]; }
    __syncthreads();
#pragma unroll
    for (int q = 0; q < 2; q++) {
        const int u = q * 256 + tid;
        const int i = u >> 4, jp = u & 15;
        const float w0 = fast_exp(t[i][2 * jp] - rm[i]) * ri[i];
        const float w1 = fast_exp(t[i][2 * jp + 1] - rm[i]) * ri[i];
        const size_t base = ((size_t)b * SDIM * SDIM + (size_t)(r0 + i) * SDIM + c0) >> 1;
        reinterpret_cast<uint32_t*>(g_Wr)[base + jp] = pack_h(w0, w1);
    }
#pragma unroll
    for (int q = 0; q < 2; q++) {
        const int u = q * 256 + tid;
        const int oc = u >> 4, ip = u & 15;
        const float w0 = fast_exp(t[2 * ip][oc] - cm[oc]) * ci[oc];
        const float w1 = fast_exp(t[2 * ip + 1][oc] - cm[oc]) * ci[oc];
        const size_t base = ((size_t)b * SDIM * SDIM + (size_t)(c0 + oc) * SDIM + r0) >> 1;
        reinterpret_cast<uint32_t*>(g_Wc)[base + ip] = pack_h(w0, w1);
    }
}

// ---------------- tensor GEMM: C = A @ B^T -----------------------------------
// PLANES=3: A=(Ah+Al), B=(Bh+Bl), 3 MMAs/step (drop lo*lo).
// PLANES=1: A=Ah, B=Bh, 1 MMA/step.
constexpr int BM = 128, BN = 256, KC = 64;
constexpr int NCHUNK = SDIM / KC;                 // 16
constexpr int RSTRIDE = 144;                      // 128 B + 16 pad, conflict-free
constexpr int APL = 128 * RSTRIDE;                // 18432
constexpr int BPL = 256 * RSTRIDE;                // 36864
constexpr int BUFB3 = 2 * APL + 2 * BPL;          // 110592
constexpr int BUFB1 = APL + BPL;                  // 55296
constexpr int SMEM3 = 2 * BUFB3;                  // 221184
constexpr int SMEM1 = 2 * BUFB1;                  // 110592

template<int PLANES>
__device__ __forceinline__ void load_chunk(const f16* Ah, const f16* Al,
                                           const f16* Bh, const f16* Bl,
                                           uint32_t s, int kt, int tid) {
    constexpr uint32_t BOFF = (PLANES == 3) ? 2u * APL : (uint32_t)APL;
#pragma unroll
    for (int q = 0; q < 2; q++) {                 // A: 128 rows x 8 segs
        const int blk = q * 512 + tid;
        const int row = blk >> 3, seg = blk & 7;
        const size_t go = (size_t)row * SDIM + kt + seg * 8;
        const uint32_t so = row * RSTRIDE + seg * 16;
        cp16(s + so, Ah + go);
        if (PLANES == 3) cp16(s + APL + so, Al + go);
    }
#pragma unroll
    for (int q = 0; q < 4; q++) {                 // B: 256 rows x 8 segs
        const int blk = q * 512 + tid;
        const int row = blk >> 3, seg = blk & 7;
        const size_t go = (size_t)row * SDIM + kt + seg * 8;
        const uint32_t so = row * RSTRIDE + seg * 16;
        cp16(s + BOFF + so, Bh + go);
        if (PLANES == 3) cp16(s + BOFF + BPL + so, Bl + go);
    }
}

template<int PLANES>
__global__ __launch_bounds__(512, 1)
void gemm_tc(const f16* __restrict__ Ah_, const f16* __restrict__ Al_,
             const f16* __restrict__ Bh_, const f16* __restrict__ Bl_,
             float* __restrict__ C_)
{
    extern __shared__ char smem[];
    constexpr int BUFB = (PLANES == 3) ? BUFB3 : BUFB1;
    constexpr uint32_t BOFF = (PLANES == 3) ? 2u * APL : (uint32_t)APL;

    const int b   = blockIdx.z;
    const int m0  = blockIdx.y * BM;
    const int n0  = blockIdx.x * BN;
    const int tid = threadIdx.x;
    const int lane = tid & 31, wid = tid >> 5;    // 16 warps: 4x4
    const int wm_ = (wid >> 2) * 32;
    const int wn_ = (wid & 3) * 64;

    const size_t bb = (size_t)b * SDIM * SDIM;
    const f16* Ah = Ah_ + bb + (size_t)m0 * SDIM;
    const f16* Al = (PLANES == 3) ? Al_ + bb + (size_t)m0 * SDIM : nullptr;
    const f16* Bh = Bh_ + bb + (size_t)n0 * SDIM;
    const f16* Bl = (PLANES == 3) ? Bl_ + bb + (size_t)n0 * SDIM : nullptr;

    const uint32_t sb[2] = { smem_u32(smem), smem_u32(smem) + BUFB };

    float acc[2][8][4] = {};

    load_chunk<PLANES>(Ah, Al, Bh, Bl, sb[0], 0, tid);
    CP_COMMIT();

    const uint32_t lrow = lane & 15;
    const uint32_t lkof = (lane >> 4) * 16;

    for (int c = 0; c < NCHUNK; c++) {
        if (c + 1 < NCHUNK) {
            load_chunk<PLANES>(Ah, Al, Bh, Bl, sb[(c + 1) & 1], (c + 1) * KC, tid);
            CP_COMMIT();
            CP_WAIT1();
        } else {
            CP_WAIT0();
        }
        __syncthreads();

        const uint32_t aHb = sb[c & 1];
        const uint32_t aLb = aHb + APL;
        const uint32_t bHb = aHb + BOFF;
        const uint32_t bLb = bHb + BPL;

#pragma unroll
        for (int ks = 0; ks < 4; ks++) {
            const uint32_t kby = ks * 32 + lkof;
            uint32_t bh[8][2], bl[8][2];
#pragma unroll
            for (int nj = 0; nj < 4; nj++) {
                const uint32_t boff = (wn_ + nj * 16 + lrow) * RSTRIDE + kby;
                uint32_t r[4];
                ldm4(r, bHb + boff);
                bh[nj * 2][0] = r[0]; bh[nj * 2][1] = r[2];
                bh[nj * 2 + 1][0] = r[1]; bh[nj * 2 + 1][1] = r[3];
                if (PLANES == 3) {
                    ldm4(r, bLb + boff);
                    bl[nj * 2][0] = r[0]; bl[nj * 2][1] = r[2];
                    bl[nj * 2 + 1][0] = r[1]; bl[nj * 2 + 1][1] = r[3];
                }
            }
#pragma unroll
            for (int mi = 0; mi < 2; mi++) {
                const uint32_t aoff = (wm_ + mi * 16 + lrow) * RSTRIDE + kby;
                uint32_t ah[4], al[4];
                ldm4(ah, aHb + aoff);
                if (PLANES == 3) ldm4(al, aLb + aoff);
#pragma unroll
                for (int na = 0; na < 8; na++) {
                    mma16816(acc[mi][na], ah, bh[na]);
                    if (PLANES == 3) {
                        mma16816(acc[mi][na], al, bh[na]);
                        mma16816(acc[mi][na], ah, bl[na]);
                    }
                }
            }
        }
        __syncthreads();
    }

    // ---- epilogue: direct STG.64 -------------------------------------------
    float* C = C_ + bb;
#pragma unroll
    for (int mi = 0; mi < 2; mi++) {
        const int r = m0 + wm_ + mi * 16 + (lane >> 2);
#pragma unroll
        for (int na = 0; na < 8; na++) {
            const int col = n0 + wn_ + na * 8 + (lane & 3) * 2;
            *reinterpret_cast<float2*>(C + (size_t)r * SDIM + col) =
                make_float2(acc[mi][na][0], acc[mi][na][1]);
            *reinterpret_cast<float2*>(C + (size_t)(r + 8) * SDIM + col) =
                make_float2(acc[mi][na][2], acc[mi][na][3]);
        }
    }
}

// ---------------- softmax statistics -----------------------------------------
__global__ void row_stats_kernel() {
    const int row = blockIdx.x;
    const float* e = g_e + (size_t)row * SDIM;
    const int tid = threadIdx.x;
    float4 v = *reinterpret_cast<const float4*>(e + tid * 4);
    float m = fmaxf(fmaxf(v.x, v.y), fmaxf(v.z, v.w));

    __shared__ float red[256];
    red[tid] = m;
    __syncthreads();
    for (int s = 128; s > 0; s >>= 1) {
        if (tid < s) red[tid] = fmaxf(red[tid], red[tid + s]);
        __syncthreads();
    }
    float rmax = red[0];
    __syncthreads();

    float s = fast_exp(v.x - rmax) + fast_exp(v.y - rmax)
            + fast_exp(v.z - rmax) + fast_exp(v.w - rmax);
    red[tid] = s;
    __syncthreads();
    for (int st = 128; st > 0; st >>= 1) {
        if (tid < st) red[tid] += red[tid + st];
        __syncthreads();
    }
    if (tid == 0) {
        g_rmax[row] = rmax;
        g_rinv[row] = 1.0f / red[0];
    }
}

__global__ __launch_bounds__(256, 4)
void col_stats_kernel() {
    const int b    = blockIdx.y;
    const int c0   = blockIdx.x * 128;
    const int tid  = threadIdx.x;
    const int cg   = tid & 31;
    const int rg   = tid >> 5;
    const float* e = g_e + (size_t)b * SDIM * SDIM + c0;

    __shared__ float red[8][132];

    float4 m4 = make_float4(-3.4e38f, -3.4e38f, -3.4e38f, -3.4e38f);
    for (int i = rg; i < SDIM; i += 8) {
        float4 v = *reinterpret_cast<const float4*>(e + (size_t)i * SDIM + cg * 4);
        m4.x = fmaxf(m4.x, v.x); m4.y = fmaxf(m4.y, v.y);
        m4.z = fmaxf(m4.z, v.z); m4.w = fmaxf(m4.w, v.w);
    }
    *reinterpret_cast<float4*>(&red[rg][cg * 4]) = m4;
    __syncthreads();
    float cmax[4];
    if (rg == 0) {
#pragma unroll
        for (int q = 0; q < 4; q++) {
            float m = red[0][cg * 4 + q];
#pragma unroll
            for (int r = 1; r < 8; r++) m = fmaxf(m, red[r][cg * 4 + q]);
            red[0][cg * 4 + q] = m;
        }
    }
    __syncthreads();
#pragma unroll
    for (int q = 0; q < 4; q++) cmax[q] = red[0][cg * 4 + q];
    __syncthreads();

    float4 s4 = make_float4(0.f, 0.f, 0.f, 0.f);
    for (int i = rg; i < SDIM; i += 8) {
        float4 v = *reinterpret_cast<const float4*>(e + (size_t)i * SDIM + cg * 4);
        s4.x += fast_exp(v.x - cmax[0]);
        s4.y += fast_exp(v.y - cmax[1]);
        s4.z += fast_exp(v.z - cmax[2]);
        s4.w += fast_exp(v.w - cmax[3]);
    }
    *reinterpret_cast<float4*>(&red[rg][cg * 4]) = s4;
    __syncthreads();
    if (rg == 0) {
#pragma unroll
        for (int q = 0; q < 4; q++) {
            float s = red[0][cg * 4 + q];
#pragma unroll
            for (int r = 1; r < 8; r++) s += red[r][cg * 4 + q];
            int j = c0 + cg * 4 + q;
            g_cmax[b * SDIM + j] = cmax[q];
            g_cinv[b * SDIM + j] = 1.0f / s;
        }
    }
}

// ---------------- entry ------------------------------------------------------
extern "C" void kernel_launch(void* const* d_in, const int* in_sizes, int n_in,
                              void* d_out, int out_size) {
    const float* P = (const float*)d_in[0];
    const float* H = (const float*)d_in[1];
    float* out_p = (float*)d_out;
    float* out_h = out_p + NELEM;

    cudaFuncSetAttribute((const void*)gemm_tc<3>,
                         cudaFuncAttributeMaxDynamicSharedMemorySize, SMEM3);
    cudaFuncSetAttribute((const void*)gemm_tc<1>,
                         cudaFuncAttributeMaxDynamicSharedMemorySize, SMEM1);

    f16 *Ph, *Pl, *Hh, *Hl, *HT, *PT, *Wr, *Wc;
    float* e;
    cudaGetSymbolAddress((void**)&Ph, g_Ph); cudaGetSymbolAddress((void**)&Pl, g_Pl);
    cudaGetSymbolAddress((void**)&Hh, g_Hh); cudaGetSymbolAddress((void**)&Hl, g_Hl);
    cudaGetSymbolAddress((void**)&HT, g_HT); cudaGetSymbolAddress((void**)&PT, g_PT);
    cudaGetSymbolAddress((void**)&Wr, g_Wr); cudaGetSymbolAddress((void**)&Wc, g_Wc);
    cudaGetSymbolAddress((void**)&e,  g_e);

    const int cvtBlocks = (int)(NELEM / 4 / 256);             // 32768
    cvt_kernel<<<cvtBlocks, 256>>>(P, Ph, Pl);
    cvt_kernel<<<cvtBlocks, 256>>>(H, Hh, Hl);
    tcvt_kernel<<<dim3(32, 32, BATCH), 256>>>(H, HT);
    tcvt_kernel<<<dim3(32, 32, BATCH), 256>>>(P, PT);

    dim3 gg(SDIM / BN, SDIM / BM, BATCH);                     // (4, 8, 32)
    gemm_tc<3><<<gg, 512, SMEM3>>>(Ph, Pl, Hh, Hl, e);        // e = P @ H^T

    row_stats_kernel<<<BATCH * SDIM, 256>>>();
    col_stats_kernel<<<dim3(SDIM / 128, BATCH), 256>>>();
    weights_kernel<<<dim3(32, 32, BATCH), 256>>>();

    gemm_tc<1><<<gg, 512, SMEM1>>>(Wr, nullptr, HT, nullptr, out_p);  // softmax_r(e) @ H
    gemm_tc<1><<<gg, 512, SMEM1>>>(Wc, nullptr, PT, nullptr, out_h);  // softmax_c(e)^T @ P
}

// round 10
// speedup vs baseline: 3.2978x; 1.0160x over previous
#include <cuda_runtime.h>
#include <cuda_fp16.h>
#include <cstdint>

#define SDIM 1024
#define BATCH 32
typedef __half f16;

constexpr size_t NELEM = (size_t)BATCH * SDIM * SDIM;   // 33.5M

// ---------------- scratch (device globals — no allocation allowed) ----------
__device__ float g_e[NELEM];                       // 128 MB similarity matrix
__device__ float g_rmax[BATCH * SDIM];
__device__ float g_rinv[BATCH * SDIM];
__device__ float g_cmax[BATCH * SDIM];
__device__ float g_cinv[BATCH * SDIM];
// split-fp16 planes for GEMM-1 operands
__device__ f16 g_Ph[NELEM], g_Pl[NELEM];           // P   [b][i][d] hi/lo
__device__ f16 g_Hh[NELEM], g_Hl[NELEM];           // H   [b][j][d] hi/lo
// single-fp16 planes for GEMM-2/3 operands
__device__ f16 g_HT[NELEM];                        // H^T [b][d][j]
__device__ f16 g_PT[NELEM];                        // P^T [b][d][i]
__device__ f16 g_Wr[NELEM];                        // row-softmax(e)   [b][i][j]
__device__ f16 g_Wc[NELEM];                        // col-softmax(e)^T [b][j][i]

// ---------------- fast exp on the FMA pipe ----------------------------------
__device__ __forceinline__ float fast_exp(float x) {
    float t = x * 1.4426950408889634f;
    t = fmaxf(t, -126.0f);
    float n = floorf(t);
    float f = t - n;
    float p = 1.52527338e-5f;
    p = fmaf(p, f, 1.54035304e-4f);
    p = fmaf(p, f, 1.33335581e-3f);
    p = fmaf(p, f, 9.61812911e-3f);
    p = fmaf(p, f, 5.55041087e-2f);
    p = fmaf(p, f, 2.40226507e-1f);
    p = fmaf(p, f, 6.93147181e-1f);
    p = fmaf(p, f, 1.0f);
    return p * __int_as_float(((int)n + 127) << 23);
}

// ---------------- low-level helpers ------------------------------------------
__device__ __forceinline__ uint32_t smem_u32(const void* p) {
    uint32_t a;
    asm("{ .reg .u64 t; cvta.to.shared.u64 t, %1; cvt.u32.u64 %0, t; }"
        : "=r"(a) : "l"(p));
    return a;
}
__device__ __forceinline__ void ldm4(uint32_t* r, uint32_t a) {
    asm volatile("ldmatrix.sync.aligned.m8n8.x4.shared.b16 {%0,%1,%2,%3}, [%4];"
                 : "=r"(r[0]), "=r"(r[1]), "=r"(r[2]), "=r"(r[3]) : "r"(a));
}
__device__ __forceinline__ void mma16816(float* d, const uint32_t* a,
                                         const uint32_t* b) {
    asm volatile(
        "mma.sync.aligned.m16n8k16.row.col.f32.f16.f16.f32 "
        "{%0,%1,%2,%3}, {%4,%5,%6,%7}, {%8,%9}, {%0,%1,%2,%3};"
        : "+f"(d[0]), "+f"(d[1]), "+f"(d[2]), "+f"(d[3])
        : "r"(a[0]), "r"(a[1]), "r"(a[2]), "r"(a[3]), "r"(b[0]), "r"(b[1]));
}
__device__ __forceinline__ void cp16(uint32_t dst, const void* src) {
    asm volatile("cp.async.cg.shared.global [%0], [%1], 16;"
                 :: "r"(dst), "l"(src));
}
#define CP_COMMIT() asm volatile("cp.async.commit_group;" ::: "memory")
#define CP_WAIT0()  asm volatile("cp.async.wait_group 0;" ::: "memory")
#define CP_WAIT1()  asm volatile("cp.async.wait_group 1;" ::: "memory")

// fp16 split: x = hi + lo. Packs (x0 -> low half, x1 -> high half).
__device__ __forceinline__ void splitpack(float x0, float x1,
                                          uint32_t& hi, uint32_t& lo) {
    __half2 h2 = __floats2half2_rn(x0, x1);
    float h0 = __half2float(__low2half(h2));
    float h1 = __half2float(__high2half(h2));
    __half2 l2 = __floats2half2_rn(x0 - h0, x1 - h1);
    hi = *reinterpret_cast<uint32_t*>(&h2);
    lo = *reinterpret_cast<uint32_t*>(&l2);
}
__device__ __forceinline__ uint32_t pack_h(float x0, float x1) {
    __half2 h2 = __floats2half2_rn(x0, x1);
    return *reinterpret_cast<uint32_t*>(&h2);
}

// ---------------- preprocess: fp32 -> split fp16 (direct) --------------------
__global__ __launch_bounds__(256)
void cvt_kernel(const float* __restrict__ X, f16* __restrict__ Oh,
                f16* __restrict__ Ol) {
    const size_t i4 = (size_t)blockIdx.x * 256 + threadIdx.x;  // float4 index
    float4 v = reinterpret_cast<const float4*>(X)[i4];
    uint32_t h0, l0, h1, l1;
    splitpack(v.x, v.y, h0, l0);
    splitpack(v.z, v.w, h1, l1);
    reinterpret_cast<uint2*>(Oh)[i4] = make_uint2(h0, h1);
    reinterpret_cast<uint2*>(Ol)[i4] = make_uint2(l0, l1);
}

// ---------------- preprocess: fp32 -> fp16 transposed (single plane) --------
__global__ __launch_bounds__(256)
void tcvt_kernel(const float* __restrict__ X, f16* __restrict__ T) {
    const int b = blockIdx.z, r0 = blockIdx.y * 32, c0 = blockIdx.x * 32;
    const int tid = threadIdx.x, tx = tid & 31, ty = tid >> 5;
    __shared__ float t[32][33];
    const float* Xb = X + (size_t)b * SDIM * SDIM;
#pragma unroll
    for (int q = 0; q < 4; q++)
        t[ty + 8 * q][tx] = Xb[(size_t)(r0 + ty + 8 * q) * SDIM + c0 + tx];
    __syncthreads();
#pragma unroll
    for (int q = 0; q < 2; q++) {
        const int u = q * 256 + tid;
        const int oc = u >> 4, ip = u & 15;
        const size_t base = ((size_t)b * SDIM * SDIM + (size_t)(c0 + oc) * SDIM + r0) >> 1;
        reinterpret_cast<uint32_t*>(T)[base + ip] =
            pack_h(t[2 * ip][oc], t[2 * ip + 1][oc]);
    }
}

// ---------------- preprocess: softmax weights (row direct + col transposed) --
__global__ __launch_bounds__(256)
void weights_kernel() {
    const int b = blockIdx.z, r0 = blockIdx.y * 32, c0 = blockIdx.x * 32;
    const int tid = threadIdx.x, tx = tid & 31, ty = tid >> 5;
    __shared__ float t[32][33];
    __shared__ float rm[32], ri[32], cm[32], ci[32];
    const float* eb = g_e + (size_t)b * SDIM * SDIM;
#pragma unroll
    for (int q = 0; q < 4; q++)
        t[ty + 8 * q][tx] = eb[(size_t)(r0 + ty + 8 * q) * SDIM + c0 + tx];
    if (tid < 32) { rm[tid] = g_rmax[b * SDIM + r0 + tid]; ri[tid] = g_rinv[b * SDIM + r0 + tid]; }
    else if (tid < 64) { cm[tid - 32] = g_cmax[b * SDIM + c0 + tid - 32]; ci[tid - 32] = g_cinv[b * SDIM + c0 + tid - 32]; }
    __syncthreads();
#pragma unroll
    for (int q = 0; q < 2; q++) {
        const int u = q * 256 + tid;
        const int i = u >> 4, jp = u & 15;
        const float w0 = fast_exp(t[i][2 * jp] - rm[i]) * ri[i];
        const float w1 = fast_exp(t[i][2 * jp + 1] - rm[i]) * ri[i];
        const size_t base = ((size_t)b * SDIM * SDIM + (size_t)(r0 + i) * SDIM + c0) >> 1;
        reinterpret_cast<uint32_t*>(g_Wr)[base + jp] = pack_h(w0, w1);
    }
#pragma unroll
    for (int q = 0; q < 2; q++) {
        const int u = q * 256 + tid;
        const int oc = u >> 4, ip = u & 15;
        const float w0 = fast_exp(t[2 * ip][oc] - cm[oc]) * ci[oc];
        const float w1 = fast_exp(t[2 * ip + 1][oc] - cm[oc]) * ci[oc];
        const size_t base = ((size_t)b * SDIM * SDIM + (size_t)(c0 + oc) * SDIM + r0) >> 1;
        reinterpret_cast<uint32_t*>(g_Wc)[base + ip] = pack_h(w0, w1);
    }
}

// ---------------- tensor GEMM: C = A @ B^T -----------------------------------
// 256 threads (8 warps, 2x4), BM=BN=128, warp tile 64x32 (mi=4, na=4).
// 2 CTAs/SM for cross-CTA load/MMA overlap.
// PLANES=3: A=(Ah+Al), B=(Bh+Bl), 3 MMAs/step, single smem buffer (72 KB).
// PLANES=1: A=Ah, B=Bh, 1 MMA/step, double smem buffer (2x36 KB).
constexpr int KC = 64;
constexpr int NCHUNK = SDIM / KC;                 // 16
constexpr int RSTRIDE = 144;                      // 128 B + 16 pad, conflict-free
constexpr int APL = 128 * RSTRIDE;                // 18432 per plane
constexpr int SMEM_G = 4 * APL;                   // 73728 both configs

template<int PLANES>
__device__ __forceinline__ void load_chunk(const f16* Ah, const f16* Al,
                                           const f16* Bh, const f16* Bl,
                                           uint32_t s, int kt, int tid) {
    constexpr uint32_t BOFF = (PLANES == 3) ? 2u * APL : (uint32_t)APL;
#pragma unroll
    for (int q = 0; q < 4; q++) {                 // A: 128 rows x 8 segs
        const int blk = q * 256 + tid;
        const int row = blk >> 3, seg = blk & 7;
        const size_t go = (size_t)row * SDIM + kt + seg * 8;
        const uint32_t so = row * RSTRIDE + seg * 16;
        cp16(s + so, Ah + go);
        if (PLANES == 3) cp16(s + APL + so, Al + go);
    }
#pragma unroll
    for (int q = 0; q < 4; q++) {                 // B: 128 rows x 8 segs
        const int blk = q * 256 + tid;
        const int row = blk >> 3, seg = blk & 7;
        const size_t go = (size_t)row * SDIM + kt + seg * 8;
        const uint32_t so = row * RSTRIDE + seg * 16;
        cp16(s + BOFF + so, Bh + go);
        if (PLANES == 3) cp16(s + BOFF + APL + so, Bl + go);
    }
}

template<int PLANES>
__global__ __launch_bounds__(256, 2)
void gemm_tc(const f16* __restrict__ Ah_, const f16* __restrict__ Al_,
             const f16* __restrict__ Bh_, const f16* __restrict__ Bl_,
             float* __restrict__ C_)
{
    extern __shared__ char smem[];
    constexpr uint32_t BOFF = (PLANES == 3) ? 2u * APL : (uint32_t)APL;
    constexpr int NBUF = (PLANES == 3) ? 1 : 2;
    constexpr int BUFB = (PLANES == 3) ? 4 * APL : 2 * APL;

    const int b   = blockIdx.z;
    const int m0  = blockIdx.y * 128;
    const int n0  = blockIdx.x * 128;
    const int tid = threadIdx.x;
    const int lane = tid & 31, wid = tid >> 5;    // 8 warps: 2x4
    const int wm_ = (wid >> 2) * 64;
    const int wn_ = (wid & 3) * 32;

    const size_t bb = (size_t)b * SDIM * SDIM;
    const f16* Ah = Ah_ + bb + (size_t)m0 * SDIM;
    const f16* Al = (PLANES == 3) ? Al_ + bb + (size_t)m0 * SDIM : nullptr;
    const f16* Bh = Bh_ + bb + (size_t)n0 * SDIM;
    const f16* Bl = (PLANES == 3) ? Bl_ + bb + (size_t)n0 * SDIM : nullptr;

    const uint32_t sb0 = smem_u32(smem);

    float acc[4][4][4] = {};                      // [mi][na][4]

    if (NBUF == 2) {
        load_chunk<PLANES>(Ah, Al, Bh, Bl, sb0, 0, tid);
        CP_COMMIT();
    }

    const uint32_t lrow = lane & 15;
    const uint32_t lkof = (lane >> 4) * 16;

    for (int c = 0; c < NCHUNK; c++) {
        uint32_t base;
        if (NBUF == 2) {
            if (c + 1 < NCHUNK) {
                load_chunk<PLANES>(Ah, Al, Bh, Bl, sb0 + ((c + 1) & 1) * BUFB,
                                   (c + 1) * KC, tid);
                CP_COMMIT();
                CP_WAIT1();
            } else {
                CP_WAIT0();
            }
            __syncthreads();
            base = sb0 + (c & 1) * BUFB;
        } else {
            load_chunk<PLANES>(Ah, Al, Bh, Bl, sb0, c * KC, tid);
            CP_COMMIT();
            CP_WAIT0();
            __syncthreads();
            base = sb0;
        }

        const uint32_t aHb = base;
        const uint32_t aLb = base + APL;
        const uint32_t bHb = base + BOFF;
        const uint32_t bLb = bHb + APL;

#pragma unroll
        for (int ks = 0; ks < 4; ks++) {
            const uint32_t kby = ks * 32 + lkof;
            uint32_t bh[4][2], bl[4][2];
#pragma unroll
            for (int nj = 0; nj < 2; nj++) {
                const uint32_t boff = (wn_ + nj * 16 + lrow) * RSTRIDE + kby;
                uint32_t r[4];
                ldm4(r, bHb + boff);
                bh[nj * 2][0] = r[0]; bh[nj * 2][1] = r[2];
                bh[nj * 2 + 1][0] = r[1]; bh[nj * 2 + 1][1] = r[3];
                if (PLANES == 3) {
                    ldm4(r, bLb + boff);
                    bl[nj * 2][0] = r[0]; bl[nj * 2][1] = r[2];
                    bl[nj * 2 + 1][0] = r[1]; bl[nj * 2 + 1][1] = r[3];
                }
            }
#pragma unroll
            for (int mi = 0; mi < 4; mi++) {
                const uint32_t aoff = (wm_ + mi * 16 + lrow) * RSTRIDE + kby;
                uint32_t ah[4], al[4];
                ldm4(ah, aHb + aoff);
                if (PLANES == 3) ldm4(al, aLb + aoff);
#pragma unroll
                for (int na = 0; na < 4; na++) {
                    mma16816(acc[mi][na], ah, bh[na]);
                    if (PLANES == 3) {
                        mma16816(acc[mi][na], al, bh[na]);
                        mma16816(acc[mi][na], ah, bl[na]);
                    }
                }
            }
        }
        __syncthreads();
    }

    // ---- epilogue: direct STG.64 -------------------------------------------
    float* C = C_ + bb;
#pragma unroll
    for (int mi = 0; mi < 4; mi++) {
        const int r = m0 + wm_ + mi * 16 + (lane >> 2);
#pragma unroll
        for (int na = 0; na < 4; na++) {
            const int col = n0 + wn_ + na * 8 + (lane & 3) * 2;
            *reinterpret_cast<float2*>(C + (size_t)r * SDIM + col) =
                make_float2(acc[mi][na][0], acc[mi][na][1]);
            *reinterpret_cast<float2*>(C + (size_t)(r + 8) * SDIM + col) =
                make_float2(acc[mi][na][2], acc[mi][na][3]);
        }
    }
}

// ---------------- softmax statistics -----------------------------------------
__global__ void row_stats_kernel() {
    const int row = blockIdx.x;
    const float* e = g_e + (size_t)row * SDIM;
    const int tid = threadIdx.x;
    float4 v = *reinterpret_cast<const float4*>(e + tid * 4);
    float m = fmaxf(fmaxf(v.x, v.y), fmaxf(v.z, v.w));

    __shared__ float red[256];
    red[tid] = m;
    __syncthreads();
    for (int s = 128; s > 0; s >>= 1) {
        if (tid < s) red[tid] = fmaxf(red[tid], red[tid + s]);
        __syncthreads();
    }
    float rmax = red[0];
    __syncthreads();

    float s = fast_exp(v.x - rmax) + fast_exp(v.y - rmax)
            + fast_exp(v.z - rmax) + fast_exp(v.w - rmax);
    red[tid] = s;
    __syncthreads();
    for (int st = 128; st > 0; st >>= 1) {
        if (tid < st) red[tid] += red[tid + st];
        __syncthreads();
    }
    if (tid == 0) {
        g_rmax[row] = rmax;
        g_rinv[row] = 1.0f / red[0];
    }
}

__global__ __launch_bounds__(256, 4)
void col_stats_kernel() {
    const int b    = blockIdx.y;
    const int c0   = blockIdx.x * 128;
    const int tid  = threadIdx.x;
    const int cg   = tid & 31;
    const int rg   = tid >> 5;
    const float* e = g_e + (size_t)b * SDIM * SDIM + c0;

    __shared__ float red[8][132];

    float4 m4 = make_float4(-3.4e38f, -3.4e38f, -3.4e38f, -3.4e38f);
    for (int i = rg; i < SDIM; i += 8) {
        float4 v = *reinterpret_cast<const float4*>(e + (size_t)i * SDIM + cg * 4);
        m4.x = fmaxf(m4.x, v.x); m4.y = fmaxf(m4.y, v.y);
        m4.z = fmaxf(m4.z, v.z); m4.w = fmaxf(m4.w, v.w);
    }
    *reinterpret_cast<float4*>(&red[rg][cg * 4]) = m4;
    __syncthreads();
    float cmax[4];
    if (rg == 0) {
#pragma unroll
        for (int q = 0; q < 4; q++) {
            float m = red[0][cg * 4 + q];
#pragma unroll
            for (int r = 1; r < 8; r++) m = fmaxf(m, red[r][cg * 4 + q]);
            red[0][cg * 4 + q] = m;
        }
    }
    __syncthreads();
#pragma unroll
    for (int q = 0; q < 4; q++) cmax[q] = red[0][cg * 4 + q];
    __syncthreads();

    float4 s4 = make_float4(0.f, 0.f, 0.f, 0.f);
    for (int i = rg; i < SDIM; i += 8) {
        float4 v = *reinterpret_cast<const float4*>(e + (size_t)i * SDIM + cg * 4);
        s4.x += fast_exp(v.x - cmax[0]);
        s4.y += fast_exp(v.y - cmax[1]);
        s4.z += fast_exp(v.z - cmax[2]);
        s4.w += fast_exp(v.w - cmax[3]);
    }
    *reinterpret_cast<float4*>(&red[rg][cg * 4]) = s4;
    __syncthreads();
    if (rg == 0) {
#pragma unroll
        for (int q = 0; q < 4; q++) {
            float s = red[0][cg * 4 + q];
#pragma unroll
            for (int r = 1; r < 8; r++) s += red[r][cg * 4 + q];
            int j = c0 + cg * 4 + q;
            g_cmax[b * SDIM + j] = cmax[q];
            g_cinv[b * SDIM + j] = 1.0f / s;
        }
    }
}

// ---------------- entry ------------------------------------------------------
extern "C" void kernel_launch(void* const* d_in, const int* in_sizes, int n_in,
                              void* d_out, int out_size) {
    const float* P = (const float*)d_in[0];
    const float* H = (const float*)d_in[1];
    float* out_p = (float*)d_out;
    float* out_h = out_p + NELEM;

    cudaFuncSetAttribute((const void*)gemm_tc<3>,
                         cudaFuncAttributeMaxDynamicSharedMemorySize, SMEM_G);
    cudaFuncSetAttribute((const void*)gemm_tc<1>,
                         cudaFuncAttributeMaxDynamicSharedMemorySize, SMEM_G);

    f16 *Ph, *Pl, *Hh, *Hl, *HT, *PT, *Wr, *Wc;
    float* e;
    cudaGetSymbolAddress((void**)&Ph, g_Ph); cudaGetSymbolAddress((void**)&Pl, g_Pl);
    cudaGetSymbolAddress((void**)&Hh, g_Hh); cudaGetSymbolAddress((void**)&Hl, g_Hl);
    cudaGetSymbolAddress((void**)&HT, g_HT); cudaGetSymbolAddress((void**)&PT, g_PT);
    cudaGetSymbolAddress((void**)&Wr, g_Wr); cudaGetSymbolAddress((void**)&Wc, g_Wc);
    cudaGetSymbolAddress((void**)&e,  g_e);

    const int cvtBlocks = (int)(NELEM / 4 / 256);             // 32768
    cvt_kernel<<<cvtBlocks, 256>>>(P, Ph, Pl);
    cvt_kernel<<<cvtBlocks, 256>>>(H, Hh, Hl);
    tcvt_kernel<<<dim3(32, 32, BATCH), 256>>>(H, HT);
    tcvt_kernel<<<dim3(32, 32, BATCH), 256>>>(P, PT);

    dim3 gg(SDIM / 128, SDIM / 128, BATCH);                   // (8, 8, 32)
    gemm_tc<3><<<gg, 256, SMEM_G>>>(Ph, Pl, Hh, Hl, e);       // e = P @ H^T

    row_stats_kernel<<<BATCH * SDIM, 256>>>();
    col_stats_kernel<<<dim3(SDIM / 128, BATCH), 256>>>();
    weights_kernel<<<dim3(32, 32, BATCH), 256>>>();

    gemm_tc<1><<<gg, 256, SMEM_G>>>(Wr, nullptr, HT, nullptr, out_p);  // softmax_r(e) @ H
    gemm_tc<1><<<gg, 256, SMEM_G>>>(Wc, nullptr, PT, nullptr, out_h);  // softmax_c(e)^T @ P
}